// round 4
// baseline (speedup 1.0000x reference)
#include <cuda_runtime.h>
#include <math.h>

// Problem constants
#define Bb 2
#define Tt 2048
#define Dd 1024
#define Hh 16
#define HDIM 64
#define NR (Bb*Tt)   // 4096 rows

// Scratch (allocation-free rule: __device__ globals)
__device__ float g_Q[NR*Dd];   // [B,H,T,Hd] head layout, pre-scaled by 1/8
__device__ float g_K[NR*Dd];   // [B,H,T,Hd]
__device__ float g_V[NR*Dd];   // [B,H,T,Hd]
__device__ float g_A[NR*Dd];   // attention output, [B,T,D] layout

// ---------------------------------------------------------------------------
// Tiled SGEMM:  out = (A[4096,1024] @ W[1024,1024] + bias) * scale
// MAP=0: write row-major [4096,1024]
// MAP=1: write head layout [B,H,T,Hd]
// BM=BN=128, BK=16, 256 threads, 8x8 per thread.
// ---------------------------------------------------------------------------
template<int MAP>
__global__ __launch_bounds__(256) void gemm_bias_kernel(
    const float* __restrict__ A, const float* __restrict__ W,
    const float* __restrict__ bias, float* __restrict__ out, float scale)
{
    __shared__ __align__(16) float As[16][128];
    __shared__ __align__(16) float Bs[16][128];

    const int bm = blockIdx.y;
    const int bn = blockIdx.x;
    const int tid = threadIdx.x;
    const int tx = tid & 15;   // 0..15 -> N
    const int ty = tid >> 4;   // 0..15 -> M

    float acc[8][8];
    #pragma unroll
    for (int i = 0; i < 8; i++)
        #pragma unroll
        for (int j = 0; j < 8; j++) acc[i][j] = 0.0f;

    const float* Ablk = A + (size_t)bm * 128 * Dd;

    for (int k0 = 0; k0 < Dd; k0 += 16) {
        // Load A tile 128x16 (transposed into As[k][m])
        #pragma unroll
        for (int i = 0; i < 2; i++) {
            int idx = tid + i * 256;        // 0..511 float4s
            int row = idx >> 2;             // 0..127
            int c4  = idx & 3;              // 0..3
            float4 v = *(const float4*)(Ablk + (size_t)row * Dd + k0 + c4 * 4);
            As[c4*4+0][row] = v.x;
            As[c4*4+1][row] = v.y;
            As[c4*4+2][row] = v.z;
            As[c4*4+3][row] = v.w;
        }
        // Load B tile 16x128
        #pragma unroll
        for (int i = 0; i < 2; i++) {
            int idx = tid + i * 256;        // 0..511 float4s
            int row = idx >> 5;             // 0..15
            int c4  = idx & 31;             // 0..31
            float4 v = *(const float4*)(W + (size_t)(k0 + row) * Dd + bn * 128 + c4 * 4);
            *(float4*)&Bs[row][c4*4] = v;
        }
        __syncthreads();

        #pragma unroll
        for (int k = 0; k < 16; k++) {
            float a[8], b[8];
            #pragma unroll
            for (int i = 0; i < 2; i++) {
                float4 v = *(const float4*)&As[k][ty*8 + i*4];
                a[i*4+0]=v.x; a[i*4+1]=v.y; a[i*4+2]=v.z; a[i*4+3]=v.w;
            }
            #pragma unroll
            for (int j = 0; j < 2; j++) {
                float4 v = *(const float4*)&Bs[k][tx*8 + j*4];
                b[j*4+0]=v.x; b[j*4+1]=v.y; b[j*4+2]=v.z; b[j*4+3]=v.w;
            }
            #pragma unroll
            for (int i = 0; i < 8; i++)
                #pragma unroll
                for (int j = 0; j < 8; j++)
                    acc[i][j] += a[i] * b[j];
        }
        __syncthreads();
    }

    // Epilogue
    #pragma unroll
    for (int i = 0; i < 8; i++) {
        int row = bm * 128 + ty * 8 + i;       // n in [0,4096)
        #pragma unroll
        for (int j = 0; j < 8; j++) {
            int col = bn * 128 + tx * 8 + j;   // d in [0,1024)
            float v = (acc[i][j] + bias[col]) * scale;
            if (MAP == 0) {
                out[(size_t)row * Dd + col] = v;
            } else {
                int b_ = row / Tt, t = row % Tt;
                int h = col / HDIM, hd = col % HDIM;
                out[(((size_t)b_ * Hh + h) * Tt + t) * HDIM + hd] = v;
            }
        }
    }
}

// ---------------------------------------------------------------------------
// Flash-attention (fp32, causal). One thread per query row; 128 q-rows per
// block; K/V staged in SMEM in 64-key tiles; online softmax in 16-key chunks.
// Scale (1/8) is pre-folded into g_Q.
// ---------------------------------------------------------------------------
__global__ __launch_bounds__(128) void attn_kernel()
{
    __shared__ __align__(16) float Ks[64 * 64];
    __shared__ __align__(16) float Vs[64 * 64];

    const int tid = threadIdx.x;          // 0..127
    const int bh  = blockIdx.y;           // 0..31
    const int q0  = blockIdx.x * 128;
    const int q   = q0 + tid;             // query index within (b,h)

    // Load Q row into registers
    const float4* Qrow = (const float4*)(g_Q + ((size_t)bh * Tt + q) * HDIM);
    float qreg[64];
    #pragma unroll
    for (int d4 = 0; d4 < 16; d4++) {
        float4 v = Qrow[d4];
        qreg[d4*4+0]=v.x; qreg[d4*4+1]=v.y; qreg[d4*4+2]=v.z; qreg[d4*4+3]=v.w;
    }

    float acc[64];
    #pragma unroll
    for (int d = 0; d < 64; d++) acc[d] = 0.0f;
    float m = -1e30f;
    float l = 0.0f;

    const int nkb = q0 / 64 + 2;          // key blocks needed (incl. diagonal)
    for (int kb = 0; kb < nkb; kb++) {
        const int j0 = kb * 64;
        const float4* Ksrc = (const float4*)(g_K + ((size_t)bh * Tt + j0) * HDIM);
        const float4* Vsrc = (const float4*)(g_V + ((size_t)bh * Tt + j0) * HDIM);
        __syncthreads();
        #pragma unroll
        for (int i = 0; i < 8; i++) {
            ((float4*)Ks)[tid + i*128] = Ksrc[tid + i*128];
            ((float4*)Vs)[tid + i*128] = Vsrc[tid + i*128];
        }
        __syncthreads();

        const bool maskBlk = (j0 + 64 > q0);   // block intersects diagonal

        #pragma unroll 1
        for (int sub = 0; sub < 4; sub++) {
            // scores for 16 keys
            float s[16];
            #pragma unroll
            for (int jj = 0; jj < 16; jj++) {
                const float4* kp = (const float4*)(Ks + (sub*16 + jj) * 64);
                float sv = 0.0f;
                #pragma unroll
                for (int d4 = 0; d4 < 16; d4++) {
                    float4 kv = kp[d4];
                    sv += qreg[4*d4+0] * kv.x;
                    sv += qreg[4*d4+1] * kv.y;
                    sv += qreg[4*d4+2] * kv.z;
                    sv += qreg[4*d4+3] * kv.w;
                }
                s[jj] = sv;
            }
            if (maskBlk) {
                #pragma unroll
                for (int jj = 0; jj < 16; jj++)
                    if (j0 + sub*16 + jj > q) s[jj] = -1e30f;
            }
            // online softmax update
            float mn = m;
            #pragma unroll
            for (int jj = 0; jj < 16; jj++) mn = fmaxf(mn, s[jj]);
            float corr = __expf(m - mn);
            l *= corr;
            #pragma unroll
            for (int d = 0; d < 64; d++) acc[d] *= corr;
            #pragma unroll
            for (int jj = 0; jj < 16; jj++) {
                float p = __expf(s[jj] - mn);
                l += p;
                const float4* vp = (const float4*)(Vs + (sub*16 + jj) * 64);
                #pragma unroll
                for (int d4 = 0; d4 < 16; d4++) {
                    float4 vv = vp[d4];
                    acc[4*d4+0] += p * vv.x;
                    acc[4*d4+1] += p * vv.y;
                    acc[4*d4+2] += p * vv.z;
                    acc[4*d4+3] += p * vv.w;
                }
            }
            m = mn;
        }
    }

    // write output in [B,T,D] layout
    const float inv = 1.0f / l;
    const int b_ = bh / Hh, h = bh % Hh;
    float4* outp = (float4*)(g_A + ((size_t)b_ * Tt + q) * Dd + h * HDIM);
    #pragma unroll
    for (int d4 = 0; d4 < 16; d4++) {
        float4 o;
        o.x = acc[4*d4+0] * inv;
        o.y = acc[4*d4+1] * inv;
        o.z = acc[4*d4+2] * inv;
        o.w = acc[4*d4+3] * inv;
        outp[d4] = o;
    }
}

// ---------------------------------------------------------------------------
extern "C" void kernel_launch(void* const* d_in, const int* in_sizes, int n_in,
                              void* d_out, int out_size)
{
    const float* query = (const float*)d_in[0];
    const float* key   = (const float*)d_in[1];
    const float* value = (const float*)d_in[2];
    const float* Wq = (const float*)d_in[3];
    const float* bq = (const float*)d_in[4];
    const float* Wk = (const float*)d_in[5];
    const float* bk = (const float*)d_in[6];
    const float* Wv = (const float*)d_in[7];
    const float* bv = (const float*)d_in[8];
    const float* Wo = (const float*)d_in[9];
    const float* bo = (const float*)d_in[10];
    float* out = (float*)d_out;

    float *qp, *kp, *vp, *ap;
    cudaGetSymbolAddress((void**)&qp, g_Q);
    cudaGetSymbolAddress((void**)&kp, g_K);
    cudaGetSymbolAddress((void**)&vp, g_V);
    cudaGetSymbolAddress((void**)&ap, g_A);

    dim3 ggrid(Dd / 128, NR / 128);   // (8, 32)

    // Projections (fold 1/sqrt(Hd)=0.125 into Q, bias included)
    gemm_bias_kernel<1><<<ggrid, 256>>>(query, Wq, bq, qp, 0.125f);
    gemm_bias_kernel<1><<<ggrid, 256>>>(key,   Wk, bk, kp, 1.0f);
    gemm_bias_kernel<1><<<ggrid, 256>>>(value, Wv, bv, vp, 1.0f);

    // Causal attention
    attn_kernel<<<dim3(Tt / 128, Bb * Hh), 128>>>();

    // Output projection -> d_out
    gemm_bias_kernel<0><<<ggrid, 256>>>(ap, Wo, bo, out, 1.0f);
}

// round 12
// speedup vs baseline: 1.4701x; 1.4701x over previous
#include <cuda_runtime.h>
#include <cstdint>
#include <math.h>

// Problem constants
#define Bb 2
#define Tt 2048
#define Dd 1024
#define Hh 16
#define HDIM 64
#define NR (Bb*Tt)   // 4096 rows

// Scratch (allocation-free rule: __device__ globals)
__device__ float g_Q[NR*Dd];   // [B,H,T,Hd] head layout, pre-scaled by 1/8
__device__ float g_K[NR*Dd];   // [B,H,T,Hd]
__device__ float g_V[NR*Dd];   // [B,H,T,Hd]
__device__ float g_A[NR*Dd];   // attention output, [B,T,D] layout

// ---------------------------------------------------------------------------
// Helpers
// ---------------------------------------------------------------------------
__device__ __forceinline__ float to_tf32(float x) {
    float r;
    asm("cvt.rna.tf32.f32 %0, %1;" : "=f"(r) : "f"(x));
    return r;
}

// mma.sync m16n8k8 tf32 (row.col), fp32 accumulate in-place
__device__ __forceinline__ void mma_tf32(float* d, const uint32_t* a, const uint32_t* b) {
    asm volatile(
        "mma.sync.aligned.m16n8k8.row.col.f32.tf32.tf32.f32 "
        "{%0,%1,%2,%3}, {%4,%5,%6,%7}, {%8,%9}, {%0,%1,%2,%3};"
        : "+f"(d[0]), "+f"(d[1]), "+f"(d[2]), "+f"(d[3])
        : "r"(a[0]), "r"(a[1]), "r"(a[2]), "r"(a[3]), "r"(b[0]), "r"(b[1]));
}

// ---------------------------------------------------------------------------
// tf32 tensor-core SGEMM: out = (A[4096,1024] @ W[1024,1024] + bias) * scale
// BM=128, BN=128, BK=32, 256 threads (8 warps), warp tile 64x32.
// MAP=0: row-major out. MAP=1: head layout [B,H,T,Hd].
// ---------------------------------------------------------------------------
#define SA 36    // A smem stride (floats): [128][36], m-major
#define SB 136   // B smem stride (floats): [32][136], k-major
#define NCHUNK 32

template<int MAP>
__global__ __launch_bounds__(256) void gemm_tc_kernel(
    const float* __restrict__ A, const float* __restrict__ W,
    const float* __restrict__ bias, float* __restrict__ out, float scale)
{
    __shared__ __align__(16) float As[128 * SA];   // 18432 B
    __shared__ __align__(16) float Bs[32 * SB];    // 17408 B

    const int tid = threadIdx.x;
    const int wid = tid >> 5;
    const int lid = tid & 31;
    const int g   = lid >> 2;      // group id 0..7
    const int tig = lid & 3;       // thread-in-group 0..3
    const int bm = blockIdx.y;
    const int bn = blockIdx.x;

    const int m0 = (wid & 1) * 64;   // warp M offset within block
    const int n0 = (wid >> 1) * 32;  // warp N offset within block

    // C fragments: 4 m-frags x 4 n-frags x 4 regs
    float c[4][4][4];
    #pragma unroll
    for (int mi = 0; mi < 4; mi++)
        #pragma unroll
        for (int ni = 0; ni < 4; ni++)
            #pragma unroll
            for (int r = 0; r < 4; r++) c[mi][ni][r] = 0.0f;

    const float* Ablk = A + (size_t)bm * 128 * Dd;
    const float* Wblk = W + bn * 128;

    // Staging indices (constant per thread)
    const int rowA = tid >> 3;        // 0..31 (A row base; +t*32)
    const int c4A  = tid & 7;         // 0..7  (A k-group of 4)
    const int kkB  = tid >> 5;        // 0..7  (B k row base; +t*8)
    const int lB   = tid & 31;        // 0..31 (B n-group of 4)

    float4 aS[4], bS[4];

    auto ldg_chunk = [&](int k0) {
        #pragma unroll
        for (int t = 0; t < 4; t++)
            aS[t] = *(const float4*)(Ablk + (size_t)(rowA + t * 32) * Dd + k0 + c4A * 4);
        #pragma unroll
        for (int t = 0; t < 4; t++)
            bS[t] = *(const float4*)(Wblk + (size_t)(k0 + kkB + t * 8) * Dd + lB * 4);
    };
    auto sts_chunk = [&]() {
        #pragma unroll
        for (int t = 0; t < 4; t++) {
            float4 v = aS[t];
            v.x = to_tf32(v.x); v.y = to_tf32(v.y);
            v.z = to_tf32(v.z); v.w = to_tf32(v.w);
            *(float4*)&As[(rowA + t * 32) * SA + c4A * 4] = v;
        }
        #pragma unroll
        for (int t = 0; t < 4; t++) {
            float4 v = bS[t];
            v.x = to_tf32(v.x); v.y = to_tf32(v.y);
            v.z = to_tf32(v.z); v.w = to_tf32(v.w);
            *(float4*)&Bs[(kkB + t * 8) * SB + lB * 4] = v;
        }
    };

    const uint32_t* Asu = (const uint32_t*)As;
    const uint32_t* Bsu = (const uint32_t*)Bs;

    ldg_chunk(0);
    sts_chunk();
    __syncthreads();

    for (int i = 0; i < NCHUNK; i++) {
        if (i < NCHUNK - 1) ldg_chunk((i + 1) * 32);   // overlap DRAM with compute

        #pragma unroll
        for (int ks = 0; ks < 4; ks++) {
            const int kb = ks * 8;
            uint32_t af[4][4], bf[4][2];
            #pragma unroll
            for (int mi = 0; mi < 4; mi++) {
                int base = (m0 + mi * 16 + g) * SA + kb + tig;
                af[mi][0] = Asu[base];
                af[mi][1] = Asu[base + 8 * SA];
                af[mi][2] = Asu[base + 4];
                af[mi][3] = Asu[base + 8 * SA + 4];
            }
            #pragma unroll
            for (int ni = 0; ni < 4; ni++) {
                int base = (kb + tig) * SB + n0 + ni * 8 + g;
                bf[ni][0] = Bsu[base];
                bf[ni][1] = Bsu[base + 4 * SB];
            }
            #pragma unroll
            for (int mi = 0; mi < 4; mi++)
                #pragma unroll
                for (int ni = 0; ni < 4; ni++)
                    mma_tf32(c[mi][ni], af[mi], bf[ni]);
        }

        __syncthreads();
        if (i < NCHUNK - 1) {
            sts_chunk();
            __syncthreads();
        }
    }

    // Epilogue: d0(r,c) d1(r,c+1) d2(r+8,c) d3(r+8,c+1)
    #pragma unroll
    for (int mi = 0; mi < 4; mi++) {
        const int r0 = bm * 128 + m0 + mi * 16 + g;
        #pragma unroll
        for (int ni = 0; ni < 4; ni++) {
            const int col = bn * 128 + n0 + ni * 8 + tig * 2;
            const float2 bv = *(const float2*)&bias[col];
            float2 v0, v1;
            v0.x = (c[mi][ni][0] + bv.x) * scale;
            v0.y = (c[mi][ni][1] + bv.y) * scale;
            v1.x = (c[mi][ni][2] + bv.x) * scale;
            v1.y = (c[mi][ni][3] + bv.y) * scale;
            if (MAP == 0) {
                *(float2*)&out[(size_t)r0 * Dd + col]       = v0;
                *(float2*)&out[(size_t)(r0 + 8) * Dd + col] = v1;
            } else {
                const int h = col / HDIM, hd = col % HDIM;
                int b_ = r0 / Tt, t = r0 % Tt;
                *(float2*)&out[(((size_t)b_ * Hh + h) * Tt + t) * HDIM + hd] = v0;
                b_ = (r0 + 8) / Tt; t = (r0 + 8) % Tt;
                *(float2*)&out[(((size_t)b_ * Hh + h) * Tt + t) * HDIM + hd] = v1;
            }
        }
    }
}

// ---------------------------------------------------------------------------
// Flash-attention (fp32, causal) — unchanged.
// ---------------------------------------------------------------------------
__global__ __launch_bounds__(128) void attn_kernel()
{
    __shared__ __align__(16) float Ks[64 * 64];
    __shared__ __align__(16) float Vs[64 * 64];

    const int tid = threadIdx.x;          // 0..127
    const int bh  = blockIdx.y;           // 0..31
    const int q0  = blockIdx.x * 128;
    const int q   = q0 + tid;             // query index within (b,h)

    const float4* Qrow = (const float4*)(g_Q + ((size_t)bh * Tt + q) * HDIM);
    float qreg[64];
    #pragma unroll
    for (int d4 = 0; d4 < 16; d4++) {
        float4 v = Qrow[d4];
        qreg[d4*4+0]=v.x; qreg[d4*4+1]=v.y; qreg[d4*4+2]=v.z; qreg[d4*4+3]=v.w;
    }

    float acc[64];
    #pragma unroll
    for (int d = 0; d < 64; d++) acc[d] = 0.0f;
    float m = -1e30f;
    float l = 0.0f;

    const int nkb = q0 / 64 + 2;
    for (int kb = 0; kb < nkb; kb++) {
        const int j0 = kb * 64;
        const float4* Ksrc = (const float4*)(g_K + ((size_t)bh * Tt + j0) * HDIM);
        const float4* Vsrc = (const float4*)(g_V + ((size_t)bh * Tt + j0) * HDIM);
        __syncthreads();
        #pragma unroll
        for (int i = 0; i < 8; i++) {
            ((float4*)Ks)[tid + i*128] = Ksrc[tid + i*128];
            ((float4*)Vs)[tid + i*128] = Vsrc[tid + i*128];
        }
        __syncthreads();

        const bool maskBlk = (j0 + 64 > q0);

        #pragma unroll 1
        for (int sub = 0; sub < 4; sub++) {
            float s[16];
            #pragma unroll
            for (int jj = 0; jj < 16; jj++) {
                const float4* kp = (const float4*)(Ks + (sub*16 + jj) * 64);
                float sv = 0.0f;
                #pragma unroll
                for (int d4 = 0; d4 < 16; d4++) {
                    float4 kv = kp[d4];
                    sv += qreg[4*d4+0] * kv.x;
                    sv += qreg[4*d4+1] * kv.y;
                    sv += qreg[4*d4+2] * kv.z;
                    sv += qreg[4*d4+3] * kv.w;
                }
                s[jj] = sv;
            }
            if (maskBlk) {
                #pragma unroll
                for (int jj = 0; jj < 16; jj++)
                    if (j0 + sub*16 + jj > q) s[jj] = -1e30f;
            }
            float mn = m;
            #pragma unroll
            for (int jj = 0; jj < 16; jj++) mn = fmaxf(mn, s[jj]);
            float corr = __expf(m - mn);
            l *= corr;
            #pragma unroll
            for (int d = 0; d < 64; d++) acc[d] *= corr;
            #pragma unroll
            for (int jj = 0; jj < 16; jj++) {
                float p = __expf(s[jj] - mn);
                l += p;
                const float4* vp = (const float4*)(Vs + (sub*16 + jj) * 64);
                #pragma unroll
                for (int d4 = 0; d4 < 16; d4++) {
                    float4 vv = vp[d4];
                    acc[4*d4+0] += p * vv.x;
                    acc[4*d4+1] += p * vv.y;
                    acc[4*d4+2] += p * vv.z;
                    acc[4*d4+3] += p * vv.w;
                }
            }
            m = mn;
        }
    }

    const float inv = 1.0f / l;
    const int b_ = bh / Hh, h = bh % Hh;
    float4* outp = (float4*)(g_A + ((size_t)b_ * Tt + q) * Dd + h * HDIM);
    #pragma unroll
    for (int d4 = 0; d4 < 16; d4++) {
        float4 o;
        o.x = acc[4*d4+0] * inv;
        o.y = acc[4*d4+1] * inv;
        o.z = acc[4*d4+2] * inv;
        o.w = acc[4*d4+3] * inv;
        outp[d4] = o;
    }
}

// ---------------------------------------------------------------------------
extern "C" void kernel_launch(void* const* d_in, const int* in_sizes, int n_in,
                              void* d_out, int out_size)
{
    const float* query = (const float*)d_in[0];
    const float* key   = (const float*)d_in[1];
    const float* value = (const float*)d_in[2];
    const float* Wq = (const float*)d_in[3];
    const float* bq = (const float*)d_in[4];
    const float* Wk = (const float*)d_in[5];
    const float* bk = (const float*)d_in[6];
    const float* Wv = (const float*)d_in[7];
    const float* bv = (const float*)d_in[8];
    const float* Wo = (const float*)d_in[9];
    const float* bo = (const float*)d_in[10];
    float* out = (float*)d_out;

    float *qp, *kp, *vp, *ap;
    cudaGetSymbolAddress((void**)&qp, g_Q);
    cudaGetSymbolAddress((void**)&kp, g_K);
    cudaGetSymbolAddress((void**)&vp, g_V);
    cudaGetSymbolAddress((void**)&ap, g_A);

    dim3 ggrid(Dd / 128, NR / 128);   // (8, 32)

    // Projections on tf32 mma.sync (fold 1/sqrt(Hd)=0.125 into Q, bias included)
    gemm_tc_kernel<1><<<ggrid, 256>>>(query, Wq, bq, qp, 0.125f);
    gemm_tc_kernel<1><<<ggrid, 256>>>(key,   Wk, bk, kp, 1.0f);
    gemm_tc_kernel<1><<<ggrid, 256>>>(value, Wv, bv, vp, 1.0f);

    // Causal attention (fp32 SIMT, unchanged)
    attn_kernel<<<dim3(Tt / 128, Bb * Hh), 128>>>();

    // Output projection -> d_out
    gemm_tc_kernel<0><<<ggrid, 256>>>(ap, Wo, bo, out, 1.0f);
}

// round 13
// speedup vs baseline: 2.2446x; 1.5268x over previous
#include <cuda_runtime.h>
#include <cstdint>
#include <math.h>

// Problem constants
#define Bb 2
#define Tt 2048
#define Dd 1024
#define Hh 16
#define HDIM 64
#define NR (Bb*Tt)   // 4096 rows

// Scratch (allocation-free rule: __device__ globals)
__device__ float g_Q[NR*Dd];   // [B,H,T,Hd] head layout, pre-scaled by 1/8
__device__ float g_K[NR*Dd];   // [B,H,T,Hd]
__device__ float g_V[NR*Dd];   // [B,H,T,Hd]
__device__ float g_A[NR*Dd];   // attention output, [B,T,D] layout

// ---------------------------------------------------------------------------
// Helpers
// ---------------------------------------------------------------------------
__device__ __forceinline__ float to_tf32(float x) {
    float r;
    asm("cvt.rna.tf32.f32 %0, %1;" : "=f"(r) : "f"(x));
    return r;
}

// mma.sync m16n8k8 tf32 (row.col), fp32 accumulate in-place
__device__ __forceinline__ void mma_tf32(float* d, const uint32_t* a, const uint32_t* b) {
    asm volatile(
        "mma.sync.aligned.m16n8k8.row.col.f32.tf32.tf32.f32 "
        "{%0,%1,%2,%3}, {%4,%5,%6,%7}, {%8,%9}, {%0,%1,%2,%3};"
        : "+f"(d[0]), "+f"(d[1]), "+f"(d[2]), "+f"(d[3])
        : "r"(a[0]), "r"(a[1]), "r"(a[2]), "r"(a[3]), "r"(b[0]), "r"(b[1]));
}

// ---------------------------------------------------------------------------
// tf32 tensor-core SGEMM: out = (A[4096,1024] @ W[1024,1024] + bias) * scale
// (unchanged from R12)
// ---------------------------------------------------------------------------
#define SA 36    // A smem stride (floats): [128][36], m-major
#define SB 136   // B smem stride (floats): [32][136], k-major
#define NCHUNK 32

template<int MAP>
__global__ __launch_bounds__(256) void gemm_tc_kernel(
    const float* __restrict__ A, const float* __restrict__ W,
    const float* __restrict__ bias, float* __restrict__ out, float scale)
{
    __shared__ __align__(16) float As[128 * SA];   // 18432 B
    __shared__ __align__(16) float Bs[32 * SB];    // 17408 B

    const int tid = threadIdx.x;
    const int wid = tid >> 5;
    const int lid = tid & 31;
    const int g   = lid >> 2;      // group id 0..7
    const int tig = lid & 3;       // thread-in-group 0..3
    const int bm = blockIdx.y;
    const int bn = blockIdx.x;

    const int m0 = (wid & 1) * 64;   // warp M offset within block
    const int n0 = (wid >> 1) * 32;  // warp N offset within block

    float c[4][4][4];
    #pragma unroll
    for (int mi = 0; mi < 4; mi++)
        #pragma unroll
        for (int ni = 0; ni < 4; ni++)
            #pragma unroll
            for (int r = 0; r < 4; r++) c[mi][ni][r] = 0.0f;

    const float* Ablk = A + (size_t)bm * 128 * Dd;
    const float* Wblk = W + bn * 128;

    const int rowA = tid >> 3;        // 0..31 (A row base; +t*32)
    const int c4A  = tid & 7;         // 0..7  (A k-group of 4)
    const int kkB  = tid >> 5;        // 0..7  (B k row base; +t*8)
    const int lB   = tid & 31;        // 0..31 (B n-group of 4)

    float4 aS[4], bS[4];

    auto ldg_chunk = [&](int k0) {
        #pragma unroll
        for (int t = 0; t < 4; t++)
            aS[t] = *(const float4*)(Ablk + (size_t)(rowA + t * 32) * Dd + k0 + c4A * 4);
        #pragma unroll
        for (int t = 0; t < 4; t++)
            bS[t] = *(const float4*)(Wblk + (size_t)(k0 + kkB + t * 8) * Dd + lB * 4);
    };
    auto sts_chunk = [&]() {
        #pragma unroll
        for (int t = 0; t < 4; t++) {
            float4 v = aS[t];
            v.x = to_tf32(v.x); v.y = to_tf32(v.y);
            v.z = to_tf32(v.z); v.w = to_tf32(v.w);
            *(float4*)&As[(rowA + t * 32) * SA + c4A * 4] = v;
        }
        #pragma unroll
        for (int t = 0; t < 4; t++) {
            float4 v = bS[t];
            v.x = to_tf32(v.x); v.y = to_tf32(v.y);
            v.z = to_tf32(v.z); v.w = to_tf32(v.w);
            *(float4*)&Bs[(kkB + t * 8) * SB + lB * 4] = v;
        }
    };

    const uint32_t* Asu = (const uint32_t*)As;
    const uint32_t* Bsu = (const uint32_t*)Bs;

    ldg_chunk(0);
    sts_chunk();
    __syncthreads();

    for (int i = 0; i < NCHUNK; i++) {
        if (i < NCHUNK - 1) ldg_chunk((i + 1) * 32);

        #pragma unroll
        for (int ks = 0; ks < 4; ks++) {
            const int kb = ks * 8;
            uint32_t af[4][4], bf[4][2];
            #pragma unroll
            for (int mi = 0; mi < 4; mi++) {
                int base = (m0 + mi * 16 + g) * SA + kb + tig;
                af[mi][0] = Asu[base];
                af[mi][1] = Asu[base + 8 * SA];
                af[mi][2] = Asu[base + 4];
                af[mi][3] = Asu[base + 8 * SA + 4];
            }
            #pragma unroll
            for (int ni = 0; ni < 4; ni++) {
                int base = (kb + tig) * SB + n0 + ni * 8 + g;
                bf[ni][0] = Bsu[base];
                bf[ni][1] = Bsu[base + 4 * SB];
            }
            #pragma unroll
            for (int mi = 0; mi < 4; mi++)
                #pragma unroll
                for (int ni = 0; ni < 4; ni++)
                    mma_tf32(c[mi][ni], af[mi], bf[ni]);
        }

        __syncthreads();
        if (i < NCHUNK - 1) {
            sts_chunk();
            __syncthreads();
        }
    }

    #pragma unroll
    for (int mi = 0; mi < 4; mi++) {
        const int r0 = bm * 128 + m0 + mi * 16 + g;
        #pragma unroll
        for (int ni = 0; ni < 4; ni++) {
            const int col = bn * 128 + n0 + ni * 8 + tig * 2;
            const float2 bv = *(const float2*)&bias[col];
            float2 v0, v1;
            v0.x = (c[mi][ni][0] + bv.x) * scale;
            v0.y = (c[mi][ni][1] + bv.y) * scale;
            v1.x = (c[mi][ni][2] + bv.x) * scale;
            v1.y = (c[mi][ni][3] + bv.y) * scale;
            if (MAP == 0) {
                *(float2*)&out[(size_t)r0 * Dd + col]       = v0;
                *(float2*)&out[(size_t)(r0 + 8) * Dd + col] = v1;
            } else {
                const int h = col / HDIM, hd = col % HDIM;
                int b_ = r0 / Tt, t = r0 % Tt;
                *(float2*)&out[(((size_t)b_ * Hh + h) * Tt + t) * HDIM + hd] = v0;
                b_ = (r0 + 8) / Tt; t = (r0 + 8) % Tt;
                *(float2*)&out[(((size_t)b_ * Hh + h) * Tt + t) * HDIM + hd] = v1;
            }
        }
    }
}

// ---------------------------------------------------------------------------
// Tensor-core flash attention (causal), split-tf32 (3-term) for QK^T and PV.
// CTA: 128 queries (8 warps x 16 q), key tiles of 64. 256 threads.
// K tile in SMEM d-major [64d][68], V tile key-major [64k][72].
// ---------------------------------------------------------------------------
#define KST 68
#define VST 72

__global__ __launch_bounds__(256) void attn_tc_kernel()
{
    __shared__ __align__(16) float Ks[64 * KST];   // 17408 B, [d][key]
    __shared__ __align__(16) float Vs[64 * VST];   // 18432 B, [key][d]

    const int tid = threadIdx.x;
    const int wid = tid >> 5;          // 0..7
    const int lid = tid & 31;
    const int g   = lid >> 2;          // 0..7
    const int tig = lid & 3;           // 0..3
    const int bh  = blockIdx.y;        // 0..31
    const int q0  = blockIdx.x * 128;
    const int qw  = q0 + wid * 16;     // warp's first query row

    const float* Qb = g_Q + (size_t)bh * Tt * HDIM;
    const float* Kb = g_K + (size_t)bh * Tt * HDIM;
    const float* Vb = g_V + (size_t)bh * Tt * HDIM;

    // --- Q fragments (hi/lo tf32 split), 8 k-chunks of 8 ---
    float qhi[8][4], qlo[8][4];
    {
        const float* qr0 = Qb + (size_t)(qw + g) * HDIM;
        const float* qr1 = Qb + (size_t)(qw + g + 8) * HDIM;
        #pragma unroll
        for (int kd = 0; kd < 8; kd++) {
            float a0 = qr0[kd * 8 + tig];
            float a1 = qr1[kd * 8 + tig];
            float a2 = qr0[kd * 8 + tig + 4];
            float a3 = qr1[kd * 8 + tig + 4];
            qhi[kd][0] = to_tf32(a0); qlo[kd][0] = to_tf32(a0 - qhi[kd][0]);
            qhi[kd][1] = to_tf32(a1); qlo[kd][1] = to_tf32(a1 - qhi[kd][1]);
            qhi[kd][2] = to_tf32(a2); qlo[kd][2] = to_tf32(a2 - qhi[kd][2]);
            qhi[kd][3] = to_tf32(a3); qlo[kd][3] = to_tf32(a3 - qhi[kd][3]);
        }
    }

    float o[8][4];
    #pragma unroll
    for (int nf = 0; nf < 8; nf++)
        #pragma unroll
        for (int r = 0; r < 4; r++) o[nf][r] = 0.0f;
    float m0 = -1e30f, m1 = -1e30f, l0 = 0.0f, l1 = 0.0f;

    const int nkb = q0 / 64 + 2;
    for (int kb = 0; kb < nkb; kb++) {
        const int j0 = kb * 64;
        __syncthreads();
        // K tile: transpose to d-major
        #pragma unroll
        for (int i = 0; i < 4; i++) {
            int f = tid + i * 256;
            int key = f & 63, d4 = f >> 6;
            float4 kv = *(const float4*)(Kb + (size_t)(j0 + key) * HDIM + d4 * 4);
            Ks[(d4 * 4 + 0) * KST + key] = kv.x;
            Ks[(d4 * 4 + 1) * KST + key] = kv.y;
            Ks[(d4 * 4 + 2) * KST + key] = kv.z;
            Ks[(d4 * 4 + 3) * KST + key] = kv.w;
        }
        // V tile: direct copy
        #pragma unroll
        for (int i = 0; i < 4; i++) {
            int f = tid + i * 256;
            int key = f >> 4, d4 = f & 15;
            *(float4*)&Vs[key * VST + d4 * 4] =
                *(const float4*)(Vb + (size_t)(j0 + key) * HDIM + d4 * 4);
        }
        __syncthreads();

        if (j0 > qw + 15) continue;    // entirely above this warp's diagonal

        // --- scores: S = Q K^T (3-term tf32 split) ---
        float c[8][4];
        #pragma unroll
        for (int nf = 0; nf < 8; nf++)
            #pragma unroll
            for (int r = 0; r < 4; r++) c[nf][r] = 0.0f;

        #pragma unroll
        for (int kd = 0; kd < 8; kd++) {
            #pragma unroll
            for (int nf = 0; nf < 8; nf++) {
                float b0 = Ks[(kd * 8 + tig) * KST + nf * 8 + g];
                float b1 = Ks[(kd * 8 + tig + 4) * KST + nf * 8 + g];
                float bh0 = to_tf32(b0), bl0 = to_tf32(b0 - bh0);
                float bh1 = to_tf32(b1), bl1 = to_tf32(b1 - bh1);
                float bhv[2] = {bh0, bh1};
                float blv[2] = {bl0, bl1};
                mma_tf32(c[nf], (const uint32_t*)qhi[kd], (const uint32_t*)bhv);
                mma_tf32(c[nf], (const uint32_t*)qlo[kd], (const uint32_t*)bhv);
                mma_tf32(c[nf], (const uint32_t*)qhi[kd], (const uint32_t*)blv);
            }
        }

        // --- causal mask (diagonal tiles only) ---
        if (j0 + 63 > qw) {
            #pragma unroll
            for (int nf = 0; nf < 8; nf++) {
                int col = j0 + nf * 8 + tig * 2;
                if (col     > qw + g)     c[nf][0] = -1e30f;
                if (col + 1 > qw + g)     c[nf][1] = -1e30f;
                if (col     > qw + g + 8) c[nf][2] = -1e30f;
                if (col + 1 > qw + g + 8) c[nf][3] = -1e30f;
            }
        }

        // --- online softmax ---
        float mx0 = -1e30f, mx1 = -1e30f;
        #pragma unroll
        for (int nf = 0; nf < 8; nf++) {
            mx0 = fmaxf(mx0, fmaxf(c[nf][0], c[nf][1]));
            mx1 = fmaxf(mx1, fmaxf(c[nf][2], c[nf][3]));
        }
        mx0 = fmaxf(mx0, __shfl_xor_sync(0xffffffffu, mx0, 1));
        mx0 = fmaxf(mx0, __shfl_xor_sync(0xffffffffu, mx0, 2));
        mx1 = fmaxf(mx1, __shfl_xor_sync(0xffffffffu, mx1, 1));
        mx1 = fmaxf(mx1, __shfl_xor_sync(0xffffffffu, mx1, 2));
        const float mn0 = fmaxf(m0, mx0);
        const float mn1 = fmaxf(m1, mx1);
        const float cr0 = __expf(m0 - mn0);
        const float cr1 = __expf(m1 - mn1);
        m0 = mn0; m1 = mn1;

        float s0 = 0.0f, s1 = 0.0f;
        #pragma unroll
        for (int nf = 0; nf < 8; nf++) {
            c[nf][0] = __expf(c[nf][0] - mn0);
            c[nf][1] = __expf(c[nf][1] - mn0);
            c[nf][2] = __expf(c[nf][2] - mn1);
            c[nf][3] = __expf(c[nf][3] - mn1);
            s0 += c[nf][0] + c[nf][1];
            s1 += c[nf][2] + c[nf][3];
            o[nf][0] *= cr0; o[nf][1] *= cr0;
            o[nf][2] *= cr1; o[nf][3] *= cr1;
        }
        s0 += __shfl_xor_sync(0xffffffffu, s0, 1);
        s0 += __shfl_xor_sync(0xffffffffu, s0, 2);
        s1 += __shfl_xor_sync(0xffffffffu, s1, 1);
        s1 += __shfl_xor_sync(0xffffffffu, s1, 2);
        l0 = l0 * cr0 + s0;
        l1 = l1 * cr1 + s1;

        // --- PV: O += P V (3-term tf32 split), P frags via shfl ---
        const int ls0 = (g << 2) | (tig >> 1);
        const int ls1 = ls0 + 2;
        const bool sel = (tig & 1);
        #pragma unroll
        for (int kc = 0; kc < 8; kc++) {
            float v00 = __shfl_sync(0xffffffffu, c[kc][0], ls0);
            float v01 = __shfl_sync(0xffffffffu, c[kc][1], ls0);
            float v10 = __shfl_sync(0xffffffffu, c[kc][2], ls0);
            float v11 = __shfl_sync(0xffffffffu, c[kc][3], ls0);
            float w00 = __shfl_sync(0xffffffffu, c[kc][0], ls1);
            float w01 = __shfl_sync(0xffffffffu, c[kc][1], ls1);
            float w10 = __shfl_sync(0xffffffffu, c[kc][2], ls1);
            float w11 = __shfl_sync(0xffffffffu, c[kc][3], ls1);
            float a0 = sel ? v01 : v00;   // (row g,   key 8kc+tig)
            float a1 = sel ? v11 : v10;   // (row g+8, key 8kc+tig)
            float a2 = sel ? w01 : w00;   // (row g,   key 8kc+tig+4)
            float a3 = sel ? w11 : w10;   // (row g+8, key 8kc+tig+4)
            float ah[4], al[4];
            ah[0] = to_tf32(a0); al[0] = to_tf32(a0 - ah[0]);
            ah[1] = to_tf32(a1); al[1] = to_tf32(a1 - ah[1]);
            ah[2] = to_tf32(a2); al[2] = to_tf32(a2 - ah[2]);
            ah[3] = to_tf32(a3); al[3] = to_tf32(a3 - ah[3]);
            #pragma unroll
            for (int nf = 0; nf < 8; nf++) {
                float b0 = Vs[(kc * 8 + tig) * VST + nf * 8 + g];
                float b1 = Vs[(kc * 8 + tig + 4) * VST + nf * 8 + g];
                float bh0 = to_tf32(b0), bl0 = to_tf32(b0 - bh0);
                float bh1 = to_tf32(b1), bl1 = to_tf32(b1 - bh1);
                float bhv[2] = {bh0, bh1};
                float blv[2] = {bl0, bl1};
                mma_tf32(o[nf], (const uint32_t*)ah, (const uint32_t*)bhv);
                mma_tf32(o[nf], (const uint32_t*)al, (const uint32_t*)bhv);
                mma_tf32(o[nf], (const uint32_t*)ah, (const uint32_t*)blv);
            }
        }
    }

    // --- epilogue: normalize and write [B,T,D] ---
    const float inv0 = 1.0f / l0;
    const float inv1 = 1.0f / l1;
    const int b_ = bh >> 4, h = bh & 15;
    float* or0 = g_A + ((size_t)b_ * Tt + qw + g) * Dd + h * HDIM;
    float* or1 = g_A + ((size_t)b_ * Tt + qw + g + 8) * Dd + h * HDIM;
    #pragma unroll
    for (int nf = 0; nf < 8; nf++) {
        float2 v0, v1;
        v0.x = o[nf][0] * inv0; v0.y = o[nf][1] * inv0;
        v1.x = o[nf][2] * inv1; v1.y = o[nf][3] * inv1;
        *(float2*)(or0 + nf * 8 + tig * 2) = v0;
        *(float2*)(or1 + nf * 8 + tig * 2) = v1;
    }
}

// ---------------------------------------------------------------------------
extern "C" void kernel_launch(void* const* d_in, const int* in_sizes, int n_in,
                              void* d_out, int out_size)
{
    const float* query = (const float*)d_in[0];
    const float* key   = (const float*)d_in[1];
    const float* value = (const float*)d_in[2];
    const float* Wq = (const float*)d_in[3];
    const float* bq = (const float*)d_in[4];
    const float* Wk = (const float*)d_in[5];
    const float* bk = (const float*)d_in[6];
    const float* Wv = (const float*)d_in[7];
    const float* bv = (const float*)d_in[8];
    const float* Wo = (const float*)d_in[9];
    const float* bo = (const float*)d_in[10];
    float* out = (float*)d_out;

    float *qp, *kp, *vp, *ap;
    cudaGetSymbolAddress((void**)&qp, g_Q);
    cudaGetSymbolAddress((void**)&kp, g_K);
    cudaGetSymbolAddress((void**)&vp, g_V);
    cudaGetSymbolAddress((void**)&ap, g_A);

    dim3 ggrid(Dd / 128, NR / 128);   // (8, 32)

    // Projections on tf32 mma.sync (fold 1/sqrt(Hd)=0.125 into Q, bias included)
    gemm_tc_kernel<1><<<ggrid, 256>>>(query, Wq, bq, qp, 0.125f);
    gemm_tc_kernel<1><<<ggrid, 256>>>(key,   Wk, bk, kp, 1.0f);
    gemm_tc_kernel<1><<<ggrid, 256>>>(value, Wv, bv, vp, 1.0f);

    // Causal attention on tensor cores (split-tf32)
    attn_tc_kernel<<<dim3(Tt / 128, Bb * Hh), 256>>>();

    // Output projection -> d_out
    gemm_tc_kernel<0><<<ggrid, 256>>>(ap, Wo, bo, out, 1.0f);
}

// round 14
// speedup vs baseline: 2.7910x; 1.2435x over previous
#include <cuda_runtime.h>
#include <cuda_bf16.h>
#include <cstdint>
#include <math.h>

// Problem constants
#define Bb 2
#define Tt 2048
#define Dd 1024
#define Hh 16
#define HDIM 64
#define NR (Bb*Tt)   // 4096 rows

// Scratch (allocation-free rule: __device__ globals)
__device__ float g_Q[NR*Dd];   // [B,H,T,Hd] head layout, pre-scaled by 1/8
__device__ float g_K[NR*Dd];   // [B,H,T,Hd]
__device__ float g_V[NR*Dd];   // [B,H,T,Hd]
__device__ float g_A[NR*Dd];   // attention output, [B,T,D] layout

// ---------------------------------------------------------------------------
// Helpers
// ---------------------------------------------------------------------------
__device__ __forceinline__ float to_tf32(float x) {
    float r;
    asm("cvt.rna.tf32.f32 %0, %1;" : "=f"(r) : "f"(x));
    return r;
}

// mma.sync m16n8k8 tf32 (row.col), fp32 accumulate in-place
__device__ __forceinline__ void mma_tf32(float* d, const uint32_t* a, const uint32_t* b) {
    asm volatile(
        "mma.sync.aligned.m16n8k8.row.col.f32.tf32.tf32.f32 "
        "{%0,%1,%2,%3}, {%4,%5,%6,%7}, {%8,%9}, {%0,%1,%2,%3};"
        : "+f"(d[0]), "+f"(d[1]), "+f"(d[2]), "+f"(d[3])
        : "r"(a[0]), "r"(a[1]), "r"(a[2]), "r"(a[3]), "r"(b[0]), "r"(b[1]));
}

// ---------------------------------------------------------------------------
// tf32 tensor-core SGEMM: out = (A[4096,1024] @ W[1024,1024] + bias) * scale
// (unchanged from R12/R13)
// ---------------------------------------------------------------------------
#define SA 36    // A smem stride (floats): [128][36], m-major
#define SB 136   // B smem stride (floats): [32][136], k-major
#define NCHUNK 32

template<int MAP>
__global__ __launch_bounds__(256) void gemm_tc_kernel(
    const float* __restrict__ A, const float* __restrict__ W,
    const float* __restrict__ bias, float* __restrict__ out, float scale)
{
    __shared__ __align__(16) float As[128 * SA];   // 18432 B
    __shared__ __align__(16) float Bs[32 * SB];    // 17408 B

    const int tid = threadIdx.x;
    const int wid = tid >> 5;
    const int lid = tid & 31;
    const int g   = lid >> 2;      // group id 0..7
    const int tig = lid & 3;       // thread-in-group 0..3
    const int bm = blockIdx.y;
    const int bn = blockIdx.x;

    const int m0 = (wid & 1) * 64;   // warp M offset within block
    const int n0 = (wid >> 1) * 32;  // warp N offset within block

    float c[4][4][4];
    #pragma unroll
    for (int mi = 0; mi < 4; mi++)
        #pragma unroll
        for (int ni = 0; ni < 4; ni++)
            #pragma unroll
            for (int r = 0; r < 4; r++) c[mi][ni][r] = 0.0f;

    const float* Ablk = A + (size_t)bm * 128 * Dd;
    const float* Wblk = W + bn * 128;

    const int rowA = tid >> 3;        // 0..31 (A row base; +t*32)
    const int c4A  = tid & 7;         // 0..7  (A k-group of 4)
    const int kkB  = tid >> 5;        // 0..7  (B k row base; +t*8)
    const int lB   = tid & 31;        // 0..31 (B n-group of 4)

    float4 aS[4], bS[4];

    auto ldg_chunk = [&](int k0) {
        #pragma unroll
        for (int t = 0; t < 4; t++)
            aS[t] = *(const float4*)(Ablk + (size_t)(rowA + t * 32) * Dd + k0 + c4A * 4);
        #pragma unroll
        for (int t = 0; t < 4; t++)
            bS[t] = *(const float4*)(Wblk + (size_t)(k0 + kkB + t * 8) * Dd + lB * 4);
    };
    auto sts_chunk = [&]() {
        #pragma unroll
        for (int t = 0; t < 4; t++) {
            float4 v = aS[t];
            v.x = to_tf32(v.x); v.y = to_tf32(v.y);
            v.z = to_tf32(v.z); v.w = to_tf32(v.w);
            *(float4*)&As[(rowA + t * 32) * SA + c4A * 4] = v;
        }
        #pragma unroll
        for (int t = 0; t < 4; t++) {
            float4 v = bS[t];
            v.x = to_tf32(v.x); v.y = to_tf32(v.y);
            v.z = to_tf32(v.z); v.w = to_tf32(v.w);
            *(float4*)&Bs[(kkB + t * 8) * SB + lB * 4] = v;
        }
    };

    const uint32_t* Asu = (const uint32_t*)As;
    const uint32_t* Bsu = (const uint32_t*)Bs;

    ldg_chunk(0);
    sts_chunk();
    __syncthreads();

    for (int i = 0; i < NCHUNK; i++) {
        if (i < NCHUNK - 1) ldg_chunk((i + 1) * 32);

        #pragma unroll
        for (int ks = 0; ks < 4; ks++) {
            const int kb = ks * 8;
            uint32_t af[4][4], bf[4][2];
            #pragma unroll
            for (int mi = 0; mi < 4; mi++) {
                int base = (m0 + mi * 16 + g) * SA + kb + tig;
                af[mi][0] = Asu[base];
                af[mi][1] = Asu[base + 8 * SA];
                af[mi][2] = Asu[base + 4];
                af[mi][3] = Asu[base + 8 * SA + 4];
            }
            #pragma unroll
            for (int ni = 0; ni < 4; ni++) {
                int base = (kb + tig) * SB + n0 + ni * 8 + g;
                bf[ni][0] = Bsu[base];
                bf[ni][1] = Bsu[base + 4 * SB];
            }
            #pragma unroll
            for (int mi = 0; mi < 4; mi++)
                #pragma unroll
                for (int ni = 0; ni < 4; ni++)
                    mma_tf32(c[mi][ni], af[mi], bf[ni]);
        }

        __syncthreads();
        if (i < NCHUNK - 1) {
            sts_chunk();
            __syncthreads();
        }
    }

    #pragma unroll
    for (int mi = 0; mi < 4; mi++) {
        const int r0 = bm * 128 + m0 + mi * 16 + g;
        #pragma unroll
        for (int ni = 0; ni < 4; ni++) {
            const int col = bn * 128 + n0 + ni * 8 + tig * 2;
            const float2 bv = *(const float2*)&bias[col];
            float2 v0, v1;
            v0.x = (c[mi][ni][0] + bv.x) * scale;
            v0.y = (c[mi][ni][1] + bv.y) * scale;
            v1.x = (c[mi][ni][2] + bv.x) * scale;
            v1.y = (c[mi][ni][3] + bv.y) * scale;
            if (MAP == 0) {
                *(float2*)&out[(size_t)r0 * Dd + col]       = v0;
                *(float2*)&out[(size_t)(r0 + 8) * Dd + col] = v1;
            } else {
                const int h = col / HDIM, hd = col % HDIM;
                int b_ = r0 / Tt, t = r0 % Tt;
                *(float2*)&out[(((size_t)b_ * Hh + h) * Tt + t) * HDIM + hd] = v0;
                b_ = (r0 + 8) / Tt; t = (r0 + 8) % Tt;
                *(float2*)&out[(((size_t)b_ * Hh + h) * Tt + t) * HDIM + hd] = v1;
            }
        }
    }
}

// ---------------------------------------------------------------------------
// Tensor-core flash attention (causal).
// QK^T: 3-term split-tf32 (K pre-split in SMEM: hi=f32, lo=bf16).
// PV:   single tf32 (P rounded in regs, V pre-rounded in SMEM).
// CTA: 128 queries (8 warps x 16 q), key tiles of 64. 256 threads.
// ---------------------------------------------------------------------------
#define KST 68   // Ksh stride (f32):  bank = 4*tig+g, conflict-free
#define LST 72   // Ksl stride (bf16): word-bank = 4*tig+g/2, conflict-free
#define VST 72   // Vs stride (f32):   bank = 8*tig+g, conflict-free

__global__ __launch_bounds__(256) void attn_tc_kernel()
{
    __shared__ __align__(16) float        Ksh[64 * KST];  // 17408 B, [d][key] tf32-hi
    __shared__ __align__(16) __nv_bfloat16 Ksl[64 * LST]; //  9216 B, [d][key] lo(bf16)
    __shared__ __align__(16) float        Vs [64 * VST];  // 18432 B, [key][d] tf32

    const int tid = threadIdx.x;
    const int wid = tid >> 5;          // 0..7
    const int lid = tid & 31;
    const int g   = lid >> 2;          // 0..7
    const int tig = lid & 3;           // 0..3
    const int bh  = blockIdx.y;        // 0..31
    const int q0  = blockIdx.x * 128;
    const int qw  = q0 + wid * 16;     // warp's first query row

    const float* Qb = g_Q + (size_t)bh * Tt * HDIM;
    const float* Kb = g_K + (size_t)bh * Tt * HDIM;
    const float* Vb = g_V + (size_t)bh * Tt * HDIM;

    // --- Q fragments (hi/lo tf32 split), 8 k-chunks of 8 ---
    float qhi[8][4], qlo[8][4];
    {
        const float* qr0 = Qb + (size_t)(qw + g) * HDIM;
        const float* qr1 = Qb + (size_t)(qw + g + 8) * HDIM;
        #pragma unroll
        for (int kd = 0; kd < 8; kd++) {
            float a0 = qr0[kd * 8 + tig];
            float a1 = qr1[kd * 8 + tig];
            float a2 = qr0[kd * 8 + tig + 4];
            float a3 = qr1[kd * 8 + tig + 4];
            qhi[kd][0] = to_tf32(a0); qlo[kd][0] = to_tf32(a0 - qhi[kd][0]);
            qhi[kd][1] = to_tf32(a1); qlo[kd][1] = to_tf32(a1 - qhi[kd][1]);
            qhi[kd][2] = to_tf32(a2); qlo[kd][2] = to_tf32(a2 - qhi[kd][2]);
            qhi[kd][3] = to_tf32(a3); qlo[kd][3] = to_tf32(a3 - qhi[kd][3]);
        }
    }

    float o[8][4];
    #pragma unroll
    for (int nf = 0; nf < 8; nf++)
        #pragma unroll
        for (int r = 0; r < 4; r++) o[nf][r] = 0.0f;
    float m0 = -1e30f, m1 = -1e30f, l0 = 0.0f, l1 = 0.0f;

    const int nkb = q0 / 64 + 2;
    for (int kb = 0; kb < nkb; kb++) {
        const int j0 = kb * 64;
        __syncthreads();
        // K tile: transpose to d-major, split hi(f32)/lo(bf16) at load
        #pragma unroll
        for (int i = 0; i < 4; i++) {
            int f = tid + i * 256;
            int key = f & 63, d4 = f >> 6;
            float4 kv = *(const float4*)(Kb + (size_t)(j0 + key) * HDIM + d4 * 4);
            float h0 = to_tf32(kv.x), h1 = to_tf32(kv.y);
            float h2 = to_tf32(kv.z), h3 = to_tf32(kv.w);
            Ksh[(d4 * 4 + 0) * KST + key] = h0;
            Ksh[(d4 * 4 + 1) * KST + key] = h1;
            Ksh[(d4 * 4 + 2) * KST + key] = h2;
            Ksh[(d4 * 4 + 3) * KST + key] = h3;
            Ksl[(d4 * 4 + 0) * LST + key] = __float2bfloat16(kv.x - h0);
            Ksl[(d4 * 4 + 1) * LST + key] = __float2bfloat16(kv.y - h1);
            Ksl[(d4 * 4 + 2) * LST + key] = __float2bfloat16(kv.z - h2);
            Ksl[(d4 * 4 + 3) * LST + key] = __float2bfloat16(kv.w - h3);
        }
        // V tile: direct copy, tf32-rounded at load
        #pragma unroll
        for (int i = 0; i < 4; i++) {
            int f = tid + i * 256;
            int key = f >> 4, d4 = f & 15;
            float4 vv = *(const float4*)(Vb + (size_t)(j0 + key) * HDIM + d4 * 4);
            vv.x = to_tf32(vv.x); vv.y = to_tf32(vv.y);
            vv.z = to_tf32(vv.z); vv.w = to_tf32(vv.w);
            *(float4*)&Vs[key * VST + d4 * 4] = vv;
        }
        __syncthreads();

        if (j0 > qw + 15) continue;    // entirely above this warp's diagonal

        // --- scores: S = Q K^T (3-term split: qh*kh + ql*kh + qh*kl) ---
        float c[8][4];
        #pragma unroll
        for (int nf = 0; nf < 8; nf++)
            #pragma unroll
            for (int r = 0; r < 4; r++) c[nf][r] = 0.0f;

        #pragma unroll
        for (int kd = 0; kd < 8; kd++) {
            #pragma unroll
            for (int nf = 0; nf < 8; nf++) {
                const int r0 = (kd * 8 + tig), r1 = (kd * 8 + tig + 4);
                const int cc = nf * 8 + g;
                float bhv[2], blv[2];
                bhv[0] = Ksh[r0 * KST + cc];
                bhv[1] = Ksh[r1 * KST + cc];
                blv[0] = __bfloat162float(Ksl[r0 * LST + cc]);
                blv[1] = __bfloat162float(Ksl[r1 * LST + cc]);
                mma_tf32(c[nf], (const uint32_t*)qhi[kd], (const uint32_t*)bhv);
                mma_tf32(c[nf], (const uint32_t*)qlo[kd], (const uint32_t*)bhv);
                mma_tf32(c[nf], (const uint32_t*)qhi[kd], (const uint32_t*)blv);
            }
        }

        // --- causal mask (diagonal tiles only) ---
        if (j0 + 63 > qw) {
            #pragma unroll
            for (int nf = 0; nf < 8; nf++) {
                int col = j0 + nf * 8 + tig * 2;
                if (col     > qw + g)     c[nf][0] = -1e30f;
                if (col + 1 > qw + g)     c[nf][1] = -1e30f;
                if (col     > qw + g + 8) c[nf][2] = -1e30f;
                if (col + 1 > qw + g + 8) c[nf][3] = -1e30f;
            }
        }

        // --- online softmax ---
        float mx0 = -1e30f, mx1 = -1e30f;
        #pragma unroll
        for (int nf = 0; nf < 8; nf++) {
            mx0 = fmaxf(mx0, fmaxf(c[nf][0], c[nf][1]));
            mx1 = fmaxf(mx1, fmaxf(c[nf][2], c[nf][3]));
        }
        mx0 = fmaxf(mx0, __shfl_xor_sync(0xffffffffu, mx0, 1));
        mx0 = fmaxf(mx0, __shfl_xor_sync(0xffffffffu, mx0, 2));
        mx1 = fmaxf(mx1, __shfl_xor_sync(0xffffffffu, mx1, 1));
        mx1 = fmaxf(mx1, __shfl_xor_sync(0xffffffffu, mx1, 2));
        const float mn0 = fmaxf(m0, mx0);
        const float mn1 = fmaxf(m1, mx1);
        const float cr0 = __expf(m0 - mn0);
        const float cr1 = __expf(m1 - mn1);
        m0 = mn0; m1 = mn1;

        float s0 = 0.0f, s1 = 0.0f;
        #pragma unroll
        for (int nf = 0; nf < 8; nf++) {
            c[nf][0] = __expf(c[nf][0] - mn0);
            c[nf][1] = __expf(c[nf][1] - mn0);
            c[nf][2] = __expf(c[nf][2] - mn1);
            c[nf][3] = __expf(c[nf][3] - mn1);
            s0 += c[nf][0] + c[nf][1];
            s1 += c[nf][2] + c[nf][3];
            o[nf][0] *= cr0; o[nf][1] *= cr0;
            o[nf][2] *= cr1; o[nf][3] *= cr1;
        }
        s0 += __shfl_xor_sync(0xffffffffu, s0, 1);
        s0 += __shfl_xor_sync(0xffffffffu, s0, 2);
        s1 += __shfl_xor_sync(0xffffffffu, s1, 1);
        s1 += __shfl_xor_sync(0xffffffffu, s1, 2);
        l0 = l0 * cr0 + s0;
        l1 = l1 * cr1 + s1;

        // --- PV: O += P V, single tf32 (P frags via shfl, V pre-rounded) ---
        const int ls0 = (g << 2) | (tig >> 1);
        const int ls1 = ls0 + 2;
        const bool sel = (tig & 1);
        #pragma unroll
        for (int kc = 0; kc < 8; kc++) {
            float v00 = __shfl_sync(0xffffffffu, c[kc][0], ls0);
            float v01 = __shfl_sync(0xffffffffu, c[kc][1], ls0);
            float v10 = __shfl_sync(0xffffffffu, c[kc][2], ls0);
            float v11 = __shfl_sync(0xffffffffu, c[kc][3], ls0);
            float w00 = __shfl_sync(0xffffffffu, c[kc][0], ls1);
            float w01 = __shfl_sync(0xffffffffu, c[kc][1], ls1);
            float w10 = __shfl_sync(0xffffffffu, c[kc][2], ls1);
            float w11 = __shfl_sync(0xffffffffu, c[kc][3], ls1);
            float ah[4];
            ah[0] = to_tf32(sel ? v01 : v00);   // (row g,   key 8kc+tig)
            ah[1] = to_tf32(sel ? v11 : v10);   // (row g+8, key 8kc+tig)
            ah[2] = to_tf32(sel ? w01 : w00);   // (row g,   key 8kc+tig+4)
            ah[3] = to_tf32(sel ? w11 : w10);   // (row g+8, key 8kc+tig+4)
            #pragma unroll
            for (int nf = 0; nf < 8; nf++) {
                float bv[2];
                bv[0] = Vs[(kc * 8 + tig) * VST + nf * 8 + g];
                bv[1] = Vs[(kc * 8 + tig + 4) * VST + nf * 8 + g];
                mma_tf32(o[nf], (const uint32_t*)ah, (const uint32_t*)bv);
            }
        }
    }

    // --- epilogue: normalize and write [B,T,D] ---
    const float inv0 = 1.0f / l0;
    const float inv1 = 1.0f / l1;
    const int b_ = bh >> 4, h = bh & 15;
    float* or0 = g_A + ((size_t)b_ * Tt + qw + g) * Dd + h * HDIM;
    float* or1 = g_A + ((size_t)b_ * Tt + qw + g + 8) * Dd + h * HDIM;
    #pragma unroll
    for (int nf = 0; nf < 8; nf++) {
        float2 v0, v1;
        v0.x = o[nf][0] * inv0; v0.y = o[nf][1] * inv0;
        v1.x = o[nf][2] * inv1; v1.y = o[nf][3] * inv1;
        *(float2*)(or0 + nf * 8 + tig * 2) = v0;
        *(float2*)(or1 + nf * 8 + tig * 2) = v1;
    }
}

// ---------------------------------------------------------------------------
extern "C" void kernel_launch(void* const* d_in, const int* in_sizes, int n_in,
                              void* d_out, int out_size)
{
    const float* query = (const float*)d_in[0];
    const float* key   = (const float*)d_in[1];
    const float* value = (const float*)d_in[2];
    const float* Wq = (const float*)d_in[3];
    const float* bq = (const float*)d_in[4];
    const float* Wk = (const float*)d_in[5];
    const float* bk = (const float*)d_in[6];
    const float* Wv = (const float*)d_in[7];
    const float* bv = (const float*)d_in[8];
    const float* Wo = (const float*)d_in[9];
    const float* bo = (const float*)d_in[10];
    float* out = (float*)d_out;

    float *qp, *kp, *vp, *ap;
    cudaGetSymbolAddress((void**)&qp, g_Q);
    cudaGetSymbolAddress((void**)&kp, g_K);
    cudaGetSymbolAddress((void**)&vp, g_V);
    cudaGetSymbolAddress((void**)&ap, g_A);

    dim3 ggrid(Dd / 128, NR / 128);   // (8, 32)

    // Projections on tf32 mma.sync (fold 1/sqrt(Hd)=0.125 into Q, bias included)
    gemm_tc_kernel<1><<<ggrid, 256>>>(query, Wq, bq, qp, 0.125f);
    gemm_tc_kernel<1><<<ggrid, 256>>>(key,   Wk, bk, kp, 1.0f);
    gemm_tc_kernel<1><<<ggrid, 256>>>(value, Wv, bv, vp, 1.0f);

    // Causal attention on tensor cores
    attn_tc_kernel<<<dim3(Tt / 128, Bb * Hh), 256>>>();

    // Output projection -> d_out
    gemm_tc_kernel<0><<<ggrid, 256>>>(ap, Wo, bo, out, 1.0f);
}

// round 15
// speedup vs baseline: 2.8083x; 1.0062x over previous
#include <cuda_runtime.h>
#include <cuda_bf16.h>
#include <cstdint>
#include <math.h>

// Problem constants
#define Bb 2
#define Tt 2048
#define Dd 1024
#define Hh 16
#define HDIM 64
#define NR (Bb*Tt)   // 4096 rows

// Scratch (allocation-free rule: __device__ globals)
__device__ float g_Q[NR*Dd];   // [B,H,T,Hd] head layout, pre-scaled by 1/8
__device__ float g_K[NR*Dd];   // [B,H,T,Hd]
__device__ float g_V[NR*Dd];   // [B,H,T,Hd]
__device__ float g_A[NR*Dd];   // attention output, [B,T,D] layout

// ---------------------------------------------------------------------------
// Helpers
// ---------------------------------------------------------------------------
__device__ __forceinline__ float to_tf32(float x) {
    float r;
    asm("cvt.rna.tf32.f32 %0, %1;" : "=f"(r) : "f"(x));
    return r;
}

// pack two floats to bf16x2: lo -> low half, hi -> high half
__device__ __forceinline__ uint32_t pack_bf16(float lo, float hi) {
    uint32_t r;
    asm("cvt.rn.bf16x2.f32 %0, %1, %2;" : "=r"(r) : "f"(hi), "f"(lo));
    return r;
}
__device__ __forceinline__ float bf16lo_f(uint32_t w) { return __uint_as_float(w << 16); }
__device__ __forceinline__ float bf16hi_f(uint32_t w) { return __uint_as_float(w & 0xffff0000u); }

// mma.sync m16n8k8 tf32 (row.col), fp32 accumulate in-place
__device__ __forceinline__ void mma_tf32(float* d, const uint32_t* a, const uint32_t* b) {
    asm volatile(
        "mma.sync.aligned.m16n8k8.row.col.f32.tf32.tf32.f32 "
        "{%0,%1,%2,%3}, {%4,%5,%6,%7}, {%8,%9}, {%0,%1,%2,%3};"
        : "+f"(d[0]), "+f"(d[1]), "+f"(d[2]), "+f"(d[3])
        : "r"(a[0]), "r"(a[1]), "r"(a[2]), "r"(a[3]), "r"(b[0]), "r"(b[1]));
}

// mma.sync m16n8k16 bf16 (row.col), fp32 accumulate in-place
__device__ __forceinline__ void mma_bf16(float* d, const uint32_t* a, uint32_t b0, uint32_t b1) {
    asm volatile(
        "mma.sync.aligned.m16n8k16.row.col.f32.bf16.bf16.f32 "
        "{%0,%1,%2,%3}, {%4,%5,%6,%7}, {%8,%9}, {%0,%1,%2,%3};"
        : "+f"(d[0]), "+f"(d[1]), "+f"(d[2]), "+f"(d[3])
        : "r"(a[0]), "r"(a[1]), "r"(a[2]), "r"(a[3]), "r"(b0), "r"(b1));
}

// ---------------------------------------------------------------------------
// tf32 tensor-core SGEMM: out = (A[4096,1024] @ W[1024,1024] + bias) * scale
// (unchanged from R12/R13)
// ---------------------------------------------------------------------------
#define SA 36    // A smem stride (floats): [128][36], m-major
#define SB 136   // B smem stride (floats): [32][136], k-major
#define NCHUNK 32

template<int MAP>
__global__ __launch_bounds__(256) void gemm_tc_kernel(
    const float* __restrict__ A, const float* __restrict__ W,
    const float* __restrict__ bias, float* __restrict__ out, float scale)
{
    __shared__ __align__(16) float As[128 * SA];   // 18432 B
    __shared__ __align__(16) float Bs[32 * SB];    // 17408 B

    const int tid = threadIdx.x;
    const int wid = tid >> 5;
    const int lid = tid & 31;
    const int g   = lid >> 2;      // group id 0..7
    const int tig = lid & 3;       // thread-in-group 0..3
    const int bm = blockIdx.y;
    const int bn = blockIdx.x;

    const int m0 = (wid & 1) * 64;   // warp M offset within block
    const int n0 = (wid >> 1) * 32;  // warp N offset within block

    float c[4][4][4];
    #pragma unroll
    for (int mi = 0; mi < 4; mi++)
        #pragma unroll
        for (int ni = 0; ni < 4; ni++)
            #pragma unroll
            for (int r = 0; r < 4; r++) c[mi][ni][r] = 0.0f;

    const float* Ablk = A + (size_t)bm * 128 * Dd;
    const float* Wblk = W + bn * 128;

    const int rowA = tid >> 3;        // 0..31 (A row base; +t*32)
    const int c4A  = tid & 7;         // 0..7  (A k-group of 4)
    const int kkB  = tid >> 5;        // 0..7  (B k row base; +t*8)
    const int lB   = tid & 31;        // 0..31 (B n-group of 4)

    float4 aS[4], bS[4];

    auto ldg_chunk = [&](int k0) {
        #pragma unroll
        for (int t = 0; t < 4; t++)
            aS[t] = *(const float4*)(Ablk + (size_t)(rowA + t * 32) * Dd + k0 + c4A * 4);
        #pragma unroll
        for (int t = 0; t < 4; t++)
            bS[t] = *(const float4*)(Wblk + (size_t)(k0 + kkB + t * 8) * Dd + lB * 4);
    };
    auto sts_chunk = [&]() {
        #pragma unroll
        for (int t = 0; t < 4; t++) {
            float4 v = aS[t];
            v.x = to_tf32(v.x); v.y = to_tf32(v.y);
            v.z = to_tf32(v.z); v.w = to_tf32(v.w);
            *(float4*)&As[(rowA + t * 32) * SA + c4A * 4] = v;
        }
        #pragma unroll
        for (int t = 0; t < 4; t++) {
            float4 v = bS[t];
            v.x = to_tf32(v.x); v.y = to_tf32(v.y);
            v.z = to_tf32(v.z); v.w = to_tf32(v.w);
            *(float4*)&Bs[(kkB + t * 8) * SB + lB * 4] = v;
        }
    };

    const uint32_t* Asu = (const uint32_t*)As;
    const uint32_t* Bsu = (const uint32_t*)Bs;

    ldg_chunk(0);
    sts_chunk();
    __syncthreads();

    for (int i = 0; i < NCHUNK; i++) {
        if (i < NCHUNK - 1) ldg_chunk((i + 1) * 32);

        #pragma unroll
        for (int ks = 0; ks < 4; ks++) {
            const int kb = ks * 8;
            uint32_t af[4][4], bf[4][2];
            #pragma unroll
            for (int mi = 0; mi < 4; mi++) {
                int base = (m0 + mi * 16 + g) * SA + kb + tig;
                af[mi][0] = Asu[base];
                af[mi][1] = Asu[base + 8 * SA];
                af[mi][2] = Asu[base + 4];
                af[mi][3] = Asu[base + 8 * SA + 4];
            }
            #pragma unroll
            for (int ni = 0; ni < 4; ni++) {
                int base = (kb + tig) * SB + n0 + ni * 8 + g;
                bf[ni][0] = Bsu[base];
                bf[ni][1] = Bsu[base + 4 * SB];
            }
            #pragma unroll
            for (int mi = 0; mi < 4; mi++)
                #pragma unroll
                for (int ni = 0; ni < 4; ni++)
                    mma_tf32(c[mi][ni], af[mi], bf[ni]);
        }

        __syncthreads();
        if (i < NCHUNK - 1) {
            sts_chunk();
            __syncthreads();
        }
    }

    #pragma unroll
    for (int mi = 0; mi < 4; mi++) {
        const int r0 = bm * 128 + m0 + mi * 16 + g;
        #pragma unroll
        for (int ni = 0; ni < 4; ni++) {
            const int col = bn * 128 + n0 + ni * 8 + tig * 2;
            const float2 bv = *(const float2*)&bias[col];
            float2 v0, v1;
            v0.x = (c[mi][ni][0] + bv.x) * scale;
            v0.y = (c[mi][ni][1] + bv.y) * scale;
            v1.x = (c[mi][ni][2] + bv.x) * scale;
            v1.y = (c[mi][ni][3] + bv.y) * scale;
            if (MAP == 0) {
                *(float2*)&out[(size_t)r0 * Dd + col]       = v0;
                *(float2*)&out[(size_t)(r0 + 8) * Dd + col] = v1;
            } else {
                const int h = col / HDIM, hd = col % HDIM;
                int b_ = r0 / Tt, t = r0 % Tt;
                *(float2*)&out[(((size_t)b_ * Hh + h) * Tt + t) * HDIM + hd] = v0;
                b_ = (r0 + 8) / Tt; t = (r0 + 8) % Tt;
                *(float2*)&out[(((size_t)b_ * Hh + h) * Tt + t) * HDIM + hd] = v1;
            }
        }
    }
}

// ---------------------------------------------------------------------------
// Tensor-core flash attention (causal), bf16 m16n8k16 with 3-term hi/lo
// splits for both QK^T and PV. P frags come straight from C frags (no shfl).
// CTA: 128 queries (8 warps x 16 q), key tiles of 64. 256 threads.
// K tiles: [64 key][32 d-pair words], V tiles: [64 d][32 key-pair words],
// stride 36 words -> B-frag LDS bank = 4g+tig(+8kc): conflict-free.
// ---------------------------------------------------------------------------
#define KWS 36

__global__ __launch_bounds__(256) void attn_tc_kernel()
{
    __shared__ __align__(16) uint32_t Ksh[64 * KWS];  // 9216 B  K hi (bf16x2)
    __shared__ __align__(16) uint32_t Ksl[64 * KWS];  // 9216 B  K lo
    __shared__ __align__(16) uint32_t Vsh[64 * KWS];  // 9216 B  V hi [d][key]
    __shared__ __align__(16) uint32_t Vsl[64 * KWS];  // 9216 B  V lo

    const int tid = threadIdx.x;
    const int wid = tid >> 5;          // 0..7
    const int lid = tid & 31;
    const int g   = lid >> 2;          // 0..7
    const int tig = lid & 3;           // 0..3
    const int bh  = blockIdx.y;        // 0..31
    const int q0  = (gridDim.x - 1 - blockIdx.x) * 128;  // longest CTAs first
    const int qw  = q0 + wid * 16;     // warp's first query row

    const float* Qb = g_Q + (size_t)bh * Tt * HDIM;
    const float* Kb = g_K + (size_t)bh * Tt * HDIM;
    const float* Vb = g_V + (size_t)bh * Tt * HDIM;

    // --- Q fragments (hi/lo bf16 split, packed), 4 chunks of k16 ---
    uint32_t qh[4][4], ql[4][4];
    {
        const float* qr0 = Qb + (size_t)(qw + g) * HDIM;
        const float* qr1 = Qb + (size_t)(qw + g + 8) * HDIM;
        #pragma unroll
        for (int kc = 0; kc < 4; kc++) {
            float2 x0 = *(const float2*)(qr0 + kc * 16 + 2 * tig);
            float2 x1 = *(const float2*)(qr1 + kc * 16 + 2 * tig);
            float2 x2 = *(const float2*)(qr0 + kc * 16 + 2 * tig + 8);
            float2 x3 = *(const float2*)(qr1 + kc * 16 + 2 * tig + 8);
            qh[kc][0] = pack_bf16(x0.x, x0.y);
            qh[kc][1] = pack_bf16(x1.x, x1.y);
            qh[kc][2] = pack_bf16(x2.x, x2.y);
            qh[kc][3] = pack_bf16(x3.x, x3.y);
            ql[kc][0] = pack_bf16(x0.x - bf16lo_f(qh[kc][0]), x0.y - bf16hi_f(qh[kc][0]));
            ql[kc][1] = pack_bf16(x1.x - bf16lo_f(qh[kc][1]), x1.y - bf16hi_f(qh[kc][1]));
            ql[kc][2] = pack_bf16(x2.x - bf16lo_f(qh[kc][2]), x2.y - bf16hi_f(qh[kc][2]));
            ql[kc][3] = pack_bf16(x3.x - bf16lo_f(qh[kc][3]), x3.y - bf16hi_f(qh[kc][3]));
        }
    }

    float o[8][4];
    #pragma unroll
    for (int nf = 0; nf < 8; nf++)
        #pragma unroll
        for (int r = 0; r < 4; r++) o[nf][r] = 0.0f;
    float m0 = -1e30f, m1 = -1e30f, l0 = 0.0f, l1 = 0.0f;

    const int nkb = q0 / 64 + 2;
    for (int kb = 0; kb < nkb; kb++) {
        const int j0 = kb * 64;
        __syncthreads();
        // K tile: [key][d-pair], hi/lo split at load
        #pragma unroll
        for (int i = 0; i < 4; i++) {
            int f = tid + i * 256;
            int key = f & 63, d4 = f >> 6;
            float4 kv = *(const float4*)(Kb + (size_t)(j0 + key) * HDIM + d4 * 4);
            uint32_t h0 = pack_bf16(kv.x, kv.y);
            uint32_t h1 = pack_bf16(kv.z, kv.w);
            uint32_t l0w = pack_bf16(kv.x - bf16lo_f(h0), kv.y - bf16hi_f(h0));
            uint32_t l1w = pack_bf16(kv.z - bf16lo_f(h1), kv.w - bf16hi_f(h1));
            *(uint2*)&Ksh[key * KWS + d4 * 2] = make_uint2(h0, h1);
            *(uint2*)&Ksl[key * KWS + d4 * 2] = make_uint2(l0w, l1w);
        }
        // V tile: transpose to [d][key], hi/lo split, 16-bit scatter
        {
            __nv_bfloat16* Vh16 = (__nv_bfloat16*)Vsh;
            __nv_bfloat16* Vl16 = (__nv_bfloat16*)Vsl;
            #pragma unroll
            for (int i = 0; i < 4; i++) {
                int f = tid + i * 256;
                int key = f & 63, d4 = f >> 6;
                float4 vv = *(const float4*)(Vb + (size_t)(j0 + key) * HDIM + d4 * 4);
                float va[4] = {vv.x, vv.y, vv.z, vv.w};
                #pragma unroll
                for (int j = 0; j < 4; j++) {
                    __nv_bfloat16 hb = __float2bfloat16(va[j]);
                    __nv_bfloat16 lb = __float2bfloat16(va[j] - __bfloat162float(hb));
                    int d = d4 * 4 + j;
                    Vh16[d * (2 * KWS) + key] = hb;
                    Vl16[d * (2 * KWS) + key] = lb;
                }
            }
        }
        __syncthreads();

        if (j0 > qw + 15) continue;    // entirely above this warp's diagonal

        // --- scores: S = Q K^T (qh*kh + ql*kh + qh*kl) ---
        float c[8][4];
        #pragma unroll
        for (int nf = 0; nf < 8; nf++)
            #pragma unroll
            for (int r = 0; r < 4; r++) c[nf][r] = 0.0f;

        #pragma unroll
        for (int kc = 0; kc < 4; kc++) {
            #pragma unroll
            for (int nf = 0; nf < 8; nf++) {
                const int w0 = (nf * 8 + g) * KWS + kc * 8 + tig;
                uint32_t bh0 = Ksh[w0], bh1 = Ksh[w0 + 4];
                uint32_t bl0 = Ksl[w0], bl1 = Ksl[w0 + 4];
                mma_bf16(c[nf], qh[kc], bh0, bh1);
                mma_bf16(c[nf], ql[kc], bh0, bh1);
                mma_bf16(c[nf], qh[kc], bl0, bl1);
            }
        }

        // --- causal mask (diagonal tiles only) ---
        if (j0 + 63 > qw) {
            #pragma unroll
            for (int nf = 0; nf < 8; nf++) {
                int col = j0 + nf * 8 + tig * 2;
                if (col     > qw + g)     c[nf][0] = -1e30f;
                if (col + 1 > qw + g)     c[nf][1] = -1e30f;
                if (col     > qw + g + 8) c[nf][2] = -1e30f;
                if (col + 1 > qw + g + 8) c[nf][3] = -1e30f;
            }
        }

        // --- online softmax ---
        float mx0 = -1e30f, mx1 = -1e30f;
        #pragma unroll
        for (int nf = 0; nf < 8; nf++) {
            mx0 = fmaxf(mx0, fmaxf(c[nf][0], c[nf][1]));
            mx1 = fmaxf(mx1, fmaxf(c[nf][2], c[nf][3]));
        }
        mx0 = fmaxf(mx0, __shfl_xor_sync(0xffffffffu, mx0, 1));
        mx0 = fmaxf(mx0, __shfl_xor_sync(0xffffffffu, mx0, 2));
        mx1 = fmaxf(mx1, __shfl_xor_sync(0xffffffffu, mx1, 1));
        mx1 = fmaxf(mx1, __shfl_xor_sync(0xffffffffu, mx1, 2));
        const float mn0 = fmaxf(m0, mx0);
        const float mn1 = fmaxf(m1, mx1);
        const float cr0 = __expf(m0 - mn0);
        const float cr1 = __expf(m1 - mn1);
        m0 = mn0; m1 = mn1;

        float s0 = 0.0f, s1 = 0.0f;
        #pragma unroll
        for (int nf = 0; nf < 8; nf++) {
            c[nf][0] = __expf(c[nf][0] - mn0);
            c[nf][1] = __expf(c[nf][1] - mn0);
            c[nf][2] = __expf(c[nf][2] - mn1);
            c[nf][3] = __expf(c[nf][3] - mn1);
            s0 += c[nf][0] + c[nf][1];
            s1 += c[nf][2] + c[nf][3];
            o[nf][0] *= cr0; o[nf][1] *= cr0;
            o[nf][2] *= cr1; o[nf][3] *= cr1;
        }
        s0 += __shfl_xor_sync(0xffffffffu, s0, 1);
        s0 += __shfl_xor_sync(0xffffffffu, s0, 2);
        s1 += __shfl_xor_sync(0xffffffffu, s1, 1);
        s1 += __shfl_xor_sync(0xffffffffu, s1, 2);
        l0 = l0 * cr0 + s0;
        l1 = l1 * cr1 + s1;

        // --- PV: O += P V (ph*vh + pl*vh + ph*vl); P frags from C frags ---
        #pragma unroll
        for (int kc = 0; kc < 4; kc++) {
            uint32_t ah[4], al[4];
            ah[0] = pack_bf16(c[2*kc][0],   c[2*kc][1]);
            ah[1] = pack_bf16(c[2*kc][2],   c[2*kc][3]);
            ah[2] = pack_bf16(c[2*kc+1][0], c[2*kc+1][1]);
            ah[3] = pack_bf16(c[2*kc+1][2], c[2*kc+1][3]);
            al[0] = pack_bf16(c[2*kc][0]   - bf16lo_f(ah[0]), c[2*kc][1]   - bf16hi_f(ah[0]));
            al[1] = pack_bf16(c[2*kc][2]   - bf16lo_f(ah[1]), c[2*kc][3]   - bf16hi_f(ah[1]));
            al[2] = pack_bf16(c[2*kc+1][0] - bf16lo_f(ah[2]), c[2*kc+1][1] - bf16hi_f(ah[2]));
            al[3] = pack_bf16(c[2*kc+1][2] - bf16lo_f(ah[3]), c[2*kc+1][3] - bf16hi_f(ah[3]));
            #pragma unroll
            for (int nf = 0; nf < 8; nf++) {
                const int w0 = (nf * 8 + g) * KWS + kc * 8 + tig;
                uint32_t bh0 = Vsh[w0], bh1 = Vsh[w0 + 4];
                uint32_t bl0 = Vsl[w0], bl1 = Vsl[w0 + 4];
                mma_bf16(o[nf], ah, bh0, bh1);
                mma_bf16(o[nf], al, bh0, bh1);
                mma_bf16(o[nf], ah, bl0, bl1);
            }
        }
    }

    // --- epilogue: normalize and write [B,T,D] ---
    const float inv0 = 1.0f / l0;
    const float inv1 = 1.0f / l1;
    const int b_ = bh >> 4, h = bh & 15;
    float* or0 = g_A + ((size_t)b_ * Tt + qw + g) * Dd + h * HDIM;
    float* or1 = g_A + ((size_t)b_ * Tt + qw + g + 8) * Dd + h * HDIM;
    #pragma unroll
    for (int nf = 0; nf < 8; nf++) {
        float2 v0, v1;
        v0.x = o[nf][0] * inv0; v0.y = o[nf][1] * inv0;
        v1.x = o[nf][2] * inv1; v1.y = o[nf][3] * inv1;
        *(float2*)(or0 + nf * 8 + tig * 2) = v0;
        *(float2*)(or1 + nf * 8 + tig * 2) = v1;
    }
}

// ---------------------------------------------------------------------------
extern "C" void kernel_launch(void* const* d_in, const int* in_sizes, int n_in,
                              void* d_out, int out_size)
{
    const float* query = (const float*)d_in[0];
    const float* key   = (const float*)d_in[1];
    const float* value = (const float*)d_in[2];
    const float* Wq = (const float*)d_in[3];
    const float* bq = (const float*)d_in[4];
    const float* Wk = (const float*)d_in[5];
    const float* bk = (const float*)d_in[6];
    const float* Wv = (const float*)d_in[7];
    const float* bv = (const float*)d_in[8];
    const float* Wo = (const float*)d_in[9];
    const float* bo = (const float*)d_in[10];
    float* out = (float*)d_out;

    float *qp, *kp, *vp, *ap;
    cudaGetSymbolAddress((void**)&qp, g_Q);
    cudaGetSymbolAddress((void**)&kp, g_K);
    cudaGetSymbolAddress((void**)&vp, g_V);
    cudaGetSymbolAddress((void**)&ap, g_A);

    dim3 ggrid(Dd / 128, NR / 128);   // (8, 32)

    // Projections on tf32 mma.sync (fold 1/sqrt(Hd)=0.125 into Q, bias included)
    gemm_tc_kernel<1><<<ggrid, 256>>>(query, Wq, bq, qp, 0.125f);
    gemm_tc_kernel<1><<<ggrid, 256>>>(key,   Wk, bk, kp, 1.0f);
    gemm_tc_kernel<1><<<ggrid, 256>>>(value, Wv, bv, vp, 1.0f);

    // Causal attention on tensor cores (bf16 splits)
    attn_tc_kernel<<<dim3(Tt / 128, Bb * Hh), 256>>>();

    // Output projection -> d_out
    gemm_tc_kernel<0><<<ggrid, 256>>>(ap, Wo, bo, out, 1.0f);
}